// round 1
// baseline (speedup 1.0000x reference)
#include <cuda_runtime.h>
#include <math.h>

// Problem constants
#define NB 8     // batch
#define NL 8     // other agents
#define NK 32    // windows
#define NP 64    // pixels per window (8x8)
#define NC 256   // dim
#define NH 8     // heads
#define NDH 32   // dim per head

#define NWE (NB*NK)          // 256 ego windows
#define NWO (NB*NL*NK)       // 2048 other windows
#define EGO_OUT_SZ (NWE*NC*NP)   // 4194304 floats

// Intermediates (static device memory; no allocation)
__device__ float g_qv_e[(size_t)NWE * NP * 512];          // 32 MB: [bk][p][0:256 q | 256:512 v]
__device__ float g_kv_o[(size_t)NWE * NP * NL * 512];     // 256 MB: [bk][p][l][0:256 k | 256:512 v]
__device__ float g_o_e [(size_t)NWE * NP * NC];           // 16 MB: attention output [bk][p][256]

// ---------------------------------------------------------------------------
// Kernel 1: fused QKV projections.
//   blocks [0, 256):    ego windows  -> q (W cols 0:256)   and v (W cols 512:768)
//   blocks [256, 2304): other windows-> k (W cols 256:512) and v (W cols 512:768)
// Input feats per window are [C=256][P=64] contiguous = A^T, perfect for GEMM.
// Out[p][j] = sum_c A[c][p] * W[c][col], tile 64x64, K-stage 32, 4x4 micro.
// ---------------------------------------------------------------------------
__global__ __launch_bounds__(256) void qkv_kernel(
    const float* __restrict__ ego, const float* __restrict__ other,
    const float* __restrict__ Wego, const float* __restrict__ Woth)
{
    __shared__ float As[32 * 68];   // [cc][p], pad 68 (68%4==0 keeps float4 align)
    __shared__ float Ws[32 * 64];   // [cc][j]

    const int w = blockIdx.x;
    const int t = threadIdx.x;
    const bool is_ego = (w < NWE);

    const float* src = is_ego ? (ego + (size_t)w * (NC * NP))
                              : (other + (size_t)(w - NWE) * (NC * NP));
    const float* Wm  = is_ego ? Wego : Woth;

    const int tj = t & 15;       // column group  (warp spans all 16 -> coalesced stores)
    const int tp = t >> 4;       // pixel group

    int wo = w - NWE;
    int b = wo >> 8, l = (wo >> 5) & 7, k = wo & 31;
    const int bk = is_ego ? w : (b * NK + k);

    for (int nc = 0; nc < 8; nc++) {
        // map the 512 produced cols to actual W_qkv columns
        const int colbase = is_ego ? ((nc < 4) ? nc * 64 : nc * 64 + 256)   // q | v
                                   : (256 + nc * 64);                        // k | v
        float acc[4][4];
        #pragma unroll
        for (int i = 0; i < 4; i++)
            #pragma unroll
            for (int j = 0; j < 4; j++) acc[i][j] = 0.f;

        for (int c0 = 0; c0 < NC; c0 += 32) {
            __syncthreads();
            // stage A chunk: rows c0..c0+31, 64 px each (contiguous)
            #pragma unroll
            for (int i = t; i < 512; i += 256) {
                int cc = i >> 4, p4 = (i & 15) * 4;
                *(float4*)&As[cc * 68 + p4] =
                    *(const float4*)&src[(size_t)(c0 + cc) * NP + p4];
            }
            // stage W chunk: rows c0..c0+31, cols colbase..colbase+63 (row stride 768)
            #pragma unroll
            for (int i = t; i < 512; i += 256) {
                int cc = i >> 4, j4 = (i & 15) * 4;
                *(float4*)&Ws[cc * 64 + j4] =
                    *(const float4*)&Wm[(size_t)(c0 + cc) * 768 + colbase + j4];
            }
            __syncthreads();
            #pragma unroll
            for (int cc = 0; cc < 32; cc++) {
                float4 a  = *(float4*)&As[cc * 68 + tp * 4];
                float4 bb = *(float4*)&Ws[cc * 64 + tj * 4];
                acc[0][0] += a.x * bb.x; acc[0][1] += a.x * bb.y; acc[0][2] += a.x * bb.z; acc[0][3] += a.x * bb.w;
                acc[1][0] += a.y * bb.x; acc[1][1] += a.y * bb.y; acc[1][2] += a.y * bb.z; acc[1][3] += a.y * bb.w;
                acc[2][0] += a.z * bb.x; acc[2][1] += a.z * bb.y; acc[2][2] += a.z * bb.z; acc[2][3] += a.z * bb.w;
                acc[3][0] += a.w * bb.x; acc[3][1] += a.w * bb.y; acc[3][2] += a.w * bb.z; acc[3][3] += a.w * bb.w;
            }
        }
        // write 4x4 micro-tile
        #pragma unroll
        for (int ii = 0; ii < 4; ii++) {
            int p = tp * 4 + ii;
            float4 v = make_float4(acc[ii][0], acc[ii][1], acc[ii][2], acc[ii][3]);
            if (is_ego) {
                *(float4*)&g_qv_e[((size_t)bk * NP + p) * 512 + nc * 64 + tj * 4] = v;
            } else {
                *(float4*)&g_kv_o[(((size_t)bk * NP + p) * NL + l) * 512 + nc * 64 + tj * 4] = v;
            }
        }
    }
}

// ---------------------------------------------------------------------------
// Kernel 2: attention. One block per pixel (bk*64+p), 256 threads = 8 heads x 32 ch.
// Warp h computes q_h . k_o[l]_h over 32 channels (shuffle reduce), softmax over
// L=8, then o = sum_l a_l * v_o[l].  (q_o/k_e path is algebraically the identity.)
// ---------------------------------------------------------------------------
__global__ __launch_bounds__(256) void attn_kernel()
{
    const int pix = blockIdx.x;          // bk*64 + p
    const int t = threadIdx.x;

    const float q = g_qv_e[(size_t)pix * 512 + t];   // channel t = h*32+lane
    const size_t base = (size_t)pix * NL * 512;
    const float scale = 0.17677669529663687f;        // 1/sqrt(32)

    float scores[NL];
    #pragma unroll
    for (int l = 0; l < NL; l++) {
        float prod = q * g_kv_o[base + l * 512 + t];
        #pragma unroll
        for (int off = 16; off > 0; off >>= 1)
            prod += __shfl_xor_sync(0xffffffffu, prod, off);
        scores[l] = prod * scale;
    }
    float mx = scores[0];
    #pragma unroll
    for (int l = 1; l < NL; l++) mx = fmaxf(mx, scores[l]);
    float sum = 0.f;
    #pragma unroll
    for (int l = 0; l < NL; l++) { scores[l] = __expf(scores[l] - mx); sum += scores[l]; }
    const float inv = 1.f / sum;
    float o = 0.f;
    #pragma unroll
    for (int l = 0; l < NL; l++)
        o += scores[l] * inv * g_kv_o[base + l * 512 + 256 + t];
    g_o_e[(size_t)pix * NC + t] = o;
}

// ---------------------------------------------------------------------------
// Kernel 3: output projections + transposed store.
//   mode 0 (ego):   out_e[bk][cout][p] = o_e[bk][p][:] @ W_out_ego + b
//   mode 1 (other): r[cout][p] = v_e[bk][p][:] @ W_out_other + b, replicated x8
//     (softmax over the singleton ego axis is identically 1 -> o_o == v_e,
//      identical for every l, so compute once and fan out the stores.)
// ---------------------------------------------------------------------------
__global__ __launch_bounds__(256) void out_kernel(
    const float* __restrict__ Woe, const float* __restrict__ boe,
    const float* __restrict__ Woo, const float* __restrict__ boo,
    float* __restrict__ out)
{
    __shared__ float As[32 * 68];   // [jc][p] (transposed A chunk)
    __shared__ float Ws[32 * 64];

    const int x = blockIdx.x;
    const int bk = x >> 1;
    const int mode = x & 1;
    const float* Wm   = mode ? Woo : Woe;
    const float* bias = mode ? boo : boe;

    const int t = threadIdx.x;
    const int tj = t & 15;
    const int tp = t >> 4;

    for (int nc = 0; nc < 4; nc++) {
        float acc[4][4];
        #pragma unroll
        for (int i = 0; i < 4; i++)
            #pragma unroll
            for (int j = 0; j < 4; j++) acc[i][j] = 0.f;

        for (int c0 = 0; c0 < NC; c0 += 32) {
            __syncthreads();
            // A chunk transposed on load: As[jc][p] = A[p][c0+jc]
            #pragma unroll
            for (int i = t; i < 2048; i += 256) {
                int jc = i & 31, p = i >> 5;
                float v = mode ? g_qv_e[((size_t)bk * NP + p) * 512 + 256 + c0 + jc]
                               : g_o_e [((size_t)bk * NP + p) * NC  +       c0 + jc];
                As[jc * 68 + p] = v;
            }
            #pragma unroll
            for (int i = t; i < 512; i += 256) {
                int cc = i >> 4, j4 = (i & 15) * 4;
                *(float4*)&Ws[cc * 64 + j4] =
                    *(const float4*)&Wm[(size_t)(c0 + cc) * NC + nc * 64 + j4];
            }
            __syncthreads();
            #pragma unroll
            for (int cc = 0; cc < 32; cc++) {
                float4 a  = *(float4*)&As[cc * 68 + tp * 4];
                float4 bb = *(float4*)&Ws[cc * 64 + tj * 4];
                acc[0][0] += a.x * bb.x; acc[0][1] += a.x * bb.y; acc[0][2] += a.x * bb.z; acc[0][3] += a.x * bb.w;
                acc[1][0] += a.y * bb.x; acc[1][1] += a.y * bb.y; acc[1][2] += a.y * bb.z; acc[1][3] += a.y * bb.w;
                acc[2][0] += a.z * bb.x; acc[2][1] += a.z * bb.y; acc[2][2] += a.z * bb.z; acc[2][3] += a.z * bb.w;
                acc[3][0] += a.w * bb.x; acc[3][1] += a.w * bb.y; acc[3][2] += a.w * bb.z; acc[3][3] += a.w * bb.w;
            }
        }
        // transposed store: out[...][cout][p], p packed as float4
        #pragma unroll
        for (int jj = 0; jj < 4; jj++) {
            int cout = nc * 64 + tj * 4 + jj;
            float bv = bias[cout];
            float4 v = make_float4(acc[0][jj] + bv, acc[1][jj] + bv,
                                   acc[2][jj] + bv, acc[3][jj] + bv);
            if (mode == 0) {
                *(float4*)&out[((size_t)bk * NC + cout) * NP + tp * 4] = v;
            } else {
                int b = bk >> 5, k = bk & 31;
                #pragma unroll
                for (int l = 0; l < NL; l++) {
                    size_t idx = (size_t)EGO_OUT_SZ
                               + ((size_t)((b * NL + l) * NK + k) * NC + cout) * NP + tp * 4;
                    *(float4*)&out[idx] = v;
                }
            }
        }
    }
}

extern "C" void kernel_launch(void* const* d_in, const int* in_sizes, int n_in,
                              void* d_out, int out_size)
{
    const float* ego   = (const float*)d_in[0];
    const float* other = (const float*)d_in[1];
    const float* Wqe   = (const float*)d_in[2];
    const float* Wqo   = (const float*)d_in[3];
    const float* Woe   = (const float*)d_in[4];
    const float* boe   = (const float*)d_in[5];
    const float* Woo   = (const float*)d_in[6];
    const float* boo   = (const float*)d_in[7];
    float* out = (float*)d_out;

    qkv_kernel<<<NWE + NWO, 256>>>(ego, other, Wqe, Wqo);
    attn_kernel<<<NWE * NP, 256>>>();
    out_kernel<<<NWE * 2, 256>>>(Woe, boe, Woo, boo, out);
}

// round 5
// speedup vs baseline: 1.8288x; 1.8288x over previous
#include <cuda_runtime.h>
#include <math.h>

// Problem constants
#define NB 8
#define NL 8
#define NK 32
#define NP 64
#define NC 256
#define NH 8
#define NDH 32

#define NWE (NB*NK)          // 256 ego windows
#define NWO (NB*NL*NK)       // 2048 other windows
#define EGO_OUT_SZ (NWE*NC*NP)

// Intermediates (static device memory; no allocation)
__device__ float g_qv_e[(size_t)NWE * NP * 512];          // [bk][p][0:256 q | 256:512 v]
__device__ float g_kv_o[(size_t)NWE * NP * NL * 512];     // [bk][p][l][0:256 k | 256:512 v]
__device__ float g_o_e [(size_t)NWE * NP * NC];           // attention output

__device__ __forceinline__ unsigned f2tf(float f) {
    unsigned u;
    asm("cvt.rna.tf32.f32 %0, %1;" : "=r"(u) : "f"(f));
    return u;
}

// ---------------------------------------------------------------------------
// Kernel 1: QKV projections on the tensor pipe (mma.sync m16n8k8 tf32).
// Grid: x = window (0..2303: ego then other), y = 128-col block (0..3).
// Block: 128 threads = 4 warps; warp tile = 32 px x 64 cols.
// A (feats) per window is [C=256][P=64] in GMEM; staged to smem [k][p] pad 72
// (bank = (8k+p)%32 -> conflict-free frag loads). B (weights) staged in frag
// order: [kstep][col][8], pair (k0+r, k0+r+4) adjacent, stride 9.
// ---------------------------------------------------------------------------
__global__ __launch_bounds__(128) void qkv_mma(
    const float* __restrict__ ego, const float* __restrict__ other,
    const float* __restrict__ Wego, const float* __restrict__ Woth)
{
    __shared__ unsigned As[32 * 72];
    __shared__ unsigned Bs[4 * 128 * 9];

    const int w = blockIdx.x;
    const int j = blockIdx.y;
    const bool is_ego = (w < NWE);
    const float* src = is_ego ? ego + (size_t)w * (NC * NP)
                              : other + (size_t)(w - NWE) * (NC * NP);
    const float* Wm = is_ego ? Wego : Woth;
    // ego produces [q(0:256) | v(256:512)] -> W cols {0:256, 512:768}
    // other produces [k | v] -> W cols 256:768
    const int colbase = is_ego ? (j < 2 ? j * 128 : j * 128 + 256) : (256 + j * 128);

    const int t = threadIdx.x;
    const int warp = t >> 5, lane = t & 31;
    const int qid = lane >> 2, tid4 = lane & 3;
    const int mbase = (warp >> 1) * 32;   // pixel base of warp tile
    const int nbase = (warp & 1) * 64;    // col base of warp tile

    float acc[2][8][4];
    #pragma unroll
    for (int mt = 0; mt < 2; mt++)
        #pragma unroll
        for (int nt = 0; nt < 8; nt++)
            #pragma unroll
            for (int r = 0; r < 4; r++) acc[mt][nt][r] = 0.f;

    for (int c0 = 0; c0 < NC; c0 += 32) {
        __syncthreads();
        // stage A: 32 k-rows x 64 px (contiguous px), convert to tf32
        #pragma unroll
        for (int i = t; i < 512; i += 128) {
            int kk = i >> 4, p4 = (i & 15) * 4;
            float4 v = *(const float4*)&src[(size_t)(c0 + kk) * NP + p4];
            unsigned* d = &As[kk * 72 + p4];
            d[0] = f2tf(v.x); d[1] = f2tf(v.y); d[2] = f2tf(v.z); d[3] = f2tf(v.w);
        }
        // stage B: 32 k-rows x 128 cols into frag order
        #pragma unroll
        for (int i = t; i < 1024; i += 128) {
            int kk = i >> 5, c4 = (i & 31) * 4;
            float4 v = *(const float4*)&Wm[(size_t)(c0 + kk) * 768 + colbase + c4];
            int ks = kk >> 3;
            int idx = 2 * (kk & 3) + ((kk >> 2) & 1);   // pair (r, r+4) adjacent
            Bs[(ks * 128 + c4 + 0) * 9 + idx] = f2tf(v.x);
            Bs[(ks * 128 + c4 + 1) * 9 + idx] = f2tf(v.y);
            Bs[(ks * 128 + c4 + 2) * 9 + idx] = f2tf(v.z);
            Bs[(ks * 128 + c4 + 3) * 9 + idx] = f2tf(v.w);
        }
        __syncthreads();

        #pragma unroll
        for (int ks = 0; ks < 4; ks++) {
            const int k0 = ks * 8;
            unsigned a[2][4];
            #pragma unroll
            for (int mt = 0; mt < 2; mt++) {
                int pr = mbase + mt * 16 + qid;
                a[mt][0] = As[(k0 + tid4) * 72 + pr];
                a[mt][1] = As[(k0 + tid4) * 72 + pr + 8];
                a[mt][2] = As[(k0 + 4 + tid4) * 72 + pr];
                a[mt][3] = As[(k0 + 4 + tid4) * 72 + pr + 8];
            }
            #pragma unroll
            for (int nt = 0; nt < 8; nt++) {
                int c = nbase + nt * 8 + qid;
                unsigned b0 = Bs[(ks * 128 + c) * 9 + 2 * tid4];
                unsigned b1 = Bs[(ks * 128 + c) * 9 + 2 * tid4 + 1];
                #pragma unroll
                for (int mt = 0; mt < 2; mt++) {
                    asm volatile(
                        "mma.sync.aligned.m16n8k8.row.col.f32.tf32.tf32.f32 "
                        "{%0,%1,%2,%3}, {%4,%5,%6,%7}, {%8,%9}, {%0,%1,%2,%3};"
                        : "+f"(acc[mt][nt][0]), "+f"(acc[mt][nt][1]),
                          "+f"(acc[mt][nt][2]), "+f"(acc[mt][nt][3])
                        : "r"(a[mt][0]), "r"(a[mt][1]), "r"(a[mt][2]), "r"(a[mt][3]),
                          "r"(b0), "r"(b1));
                }
            }
        }
    }

    // epilogue: scatter C frags to the intermediate buffers
    int wo = w - NWE;
    int bo = wo >> 8, l = (wo >> 5) & 7, kk = wo & 31;
    const int bk = is_ego ? w : (bo * NK + kk);

    #pragma unroll
    for (int mt = 0; mt < 2; mt++) {
        int px = mbase + mt * 16 + qid;
        #pragma unroll
        for (int nt = 0; nt < 8; nt++) {
            int col = j * 128 + nbase + nt * 8 + 2 * tid4;
            float2 v0 = make_float2(acc[mt][nt][0], acc[mt][nt][1]);
            float2 v1 = make_float2(acc[mt][nt][2], acc[mt][nt][3]);
            if (is_ego) {
                size_t i0 = ((size_t)bk * NP + px) * 512 + col;
                size_t i1 = ((size_t)bk * NP + px + 8) * 512 + col;
                *(float2*)&g_qv_e[i0] = v0;
                *(float2*)&g_qv_e[i1] = v1;
            } else {
                size_t i0 = (((size_t)bk * NP + px) * NL + l) * 512 + col;
                size_t i1 = (((size_t)bk * NP + px + 8) * NL + l) * 512 + col;
                *(float2*)&g_kv_o[i0] = v0;
                *(float2*)&g_kv_o[i1] = v1;
            }
        }
    }
}

// ---------------------------------------------------------------------------
// Kernel 2: attention. One block per pixel, 8 heads x 32 ch.
// q_o/k_e softmax over singleton ego axis == 1 -> only ego-query path needed.
// ---------------------------------------------------------------------------
__global__ __launch_bounds__(256) void attn_kernel()
{
    const int pix = blockIdx.x;
    const int t = threadIdx.x;

    const float q = g_qv_e[(size_t)pix * 512 + t];
    const size_t base = (size_t)pix * NL * 512;
    const float scale = 0.17677669529663687f;

    float scores[NL];
    #pragma unroll
    for (int l = 0; l < NL; l++) {
        float prod = q * g_kv_o[base + l * 512 + t];
        #pragma unroll
        for (int off = 16; off > 0; off >>= 1)
            prod += __shfl_xor_sync(0xffffffffu, prod, off);
        scores[l] = prod * scale;
    }
    float mx = scores[0];
    #pragma unroll
    for (int l = 1; l < NL; l++) mx = fmaxf(mx, scores[l]);
    float sum = 0.f;
    #pragma unroll
    for (int l = 0; l < NL; l++) { scores[l] = __expf(scores[l] - mx); sum += scores[l]; }
    const float inv = 1.f / sum;
    float o = 0.f;
    #pragma unroll
    for (int l = 0; l < NL; l++)
        o += scores[l] * inv * g_kv_o[base + l * 512 + 256 + t];
    g_o_e[(size_t)pix * NC + t] = o;
}

// ---------------------------------------------------------------------------
// Kernel 3: output projections + transposed store.
// mode 1 exploits softmax-over-singleton == identity: o_o == v_e, same for
// every l -> compute once, fan out 8 stores.
// ---------------------------------------------------------------------------
__global__ __launch_bounds__(256) void out_kernel(
    const float* __restrict__ Woe, const float* __restrict__ boe,
    const float* __restrict__ Woo, const float* __restrict__ boo,
    float* __restrict__ out)
{
    __shared__ float As[32 * 68];
    __shared__ float Ws[32 * 64];

    const int x = blockIdx.x;
    const int bk = x >> 1;
    const int mode = x & 1;
    const float* Wm   = mode ? Woo : Woe;
    const float* bias = mode ? boo : boe;

    const int t = threadIdx.x;
    const int tj = t & 15;
    const int tp = t >> 4;

    for (int nc = 0; nc < 4; nc++) {
        float acc[4][4];
        #pragma unroll
        for (int i = 0; i < 4; i++)
            #pragma unroll
            for (int jx = 0; jx < 4; jx++) acc[i][jx] = 0.f;

        for (int c0 = 0; c0 < NC; c0 += 32) {
            __syncthreads();
            #pragma unroll
            for (int i = t; i < 2048; i += 256) {
                int jc = i & 31, p = i >> 5;
                float v = mode ? g_qv_e[((size_t)bk * NP + p) * 512 + 256 + c0 + jc]
                               : g_o_e [((size_t)bk * NP + p) * NC  +       c0 + jc];
                As[jc * 68 + p] = v;
            }
            #pragma unroll
            for (int i = t; i < 512; i += 256) {
                int cc = i >> 4, j4 = (i & 15) * 4;
                *(float4*)&Ws[cc * 64 + j4] =
                    *(const float4*)&Wm[(size_t)(c0 + cc) * NC + nc * 64 + j4];
            }
            __syncthreads();
            #pragma unroll
            for (int cc = 0; cc < 32; cc++) {
                float4 a  = *(float4*)&As[cc * 68 + tp * 4];
                float4 bb = *(float4*)&Ws[cc * 64 + tj * 4];
                acc[0][0] += a.x * bb.x; acc[0][1] += a.x * bb.y; acc[0][2] += a.x * bb.z; acc[0][3] += a.x * bb.w;
                acc[1][0] += a.y * bb.x; acc[1][1] += a.y * bb.y; acc[1][2] += a.y * bb.z; acc[1][3] += a.y * bb.w;
                acc[2][0] += a.z * bb.x; acc[2][1] += a.z * bb.y; acc[2][2] += a.z * bb.z; acc[2][3] += a.z * bb.w;
                acc[3][0] += a.w * bb.x; acc[3][1] += a.w * bb.y; acc[3][2] += a.w * bb.z; acc[3][3] += a.w * bb.w;
            }
        }
        #pragma unroll
        for (int jj = 0; jj < 4; jj++) {
            int cout = nc * 64 + tj * 4 + jj;
            float bv = bias[cout];
            float4 v = make_float4(acc[0][jj] + bv, acc[1][jj] + bv,
                                   acc[2][jj] + bv, acc[3][jj] + bv);
            if (mode == 0) {
                *(float4*)&out[((size_t)bk * NC + cout) * NP + tp * 4] = v;
            } else {
                int b = bk >> 5, k = bk & 31;
                #pragma unroll
                for (int l = 0; l < NL; l++) {
                    size_t idx = (size_t)EGO_OUT_SZ
                               + ((size_t)((b * NL + l) * NK + k) * NC + cout) * NP + tp * 4;
                    *(float4*)&out[idx] = v;
                }
            }
        }
    }
}

extern "C" void kernel_launch(void* const* d_in, const int* in_sizes, int n_in,
                              void* d_out, int out_size)
{
    const float* ego   = (const float*)d_in[0];
    const float* other = (const float*)d_in[1];
    const float* Wqe   = (const float*)d_in[2];
    const float* Wqo   = (const float*)d_in[3];
    const float* Woe   = (const float*)d_in[4];
    const float* boe   = (const float*)d_in[5];
    const float* Woo   = (const float*)d_in[6];
    const float* boo   = (const float*)d_in[7];
    float* out = (float*)d_out;

    dim3 qgrid(NWE + NWO, 4);
    qkv_mma<<<qgrid, 128>>>(ego, other, Wqe, Wqo);
    attn_kernel<<<NWE * NP, 256>>>();
    out_kernel<<<NWE * 2, 256>>>(Woe, boe, Woo, boo, out);
}

// round 9
// speedup vs baseline: 2.5502x; 1.3945x over previous
#include <cuda_runtime.h>
#include <cuda_fp16.h>
#include <cstdint>
#include <math.h>

// Problem constants
#define NB 8
#define NL 8
#define NK 32
#define NP 64
#define NC 256

#define NWE 256              // ego windows
#define NWO 2048             // other windows
#define EGO_OUT_SZ (NWE*NC*NP)

// Intermediates (static device memory; no allocation)
__device__ float g_qv_e[(size_t)NWE * NP * 512];
__device__ float g_kv_o[(size_t)NWE * NP * NL * 512];
__device__ float g_o_e [(size_t)NWE * NP * NC];
__device__ __half g_Whe[256 * 768];   // fp16 copies of the QKV weights
__device__ __half g_Who[256 * 768];

__device__ __forceinline__ uint32_t smem_u32(const void* p) {
    uint32_t a;
    asm("{ .reg .u64 t; cvta.to.shared.u64 t, %1; cvt.u32.u64 %0, t; }" : "=r"(a) : "l"(p));
    return a;
}
__device__ __forceinline__ uint32_t pkh2(float x, float y) {
    __half2 h = __floats2half2_rn(x, y);
    return *(uint32_t*)&h;
}

#define LDMX4(r, addr) \
    asm volatile("ldmatrix.sync.aligned.m8n8.x4.shared.b16 {%0,%1,%2,%3}, [%4];" \
        : "=r"((r)[0]), "=r"((r)[1]), "=r"((r)[2]), "=r"((r)[3]) : "r"(addr))
#define LDMX4T(r, addr) \
    asm volatile("ldmatrix.sync.aligned.m8n8.x4.trans.shared.b16 {%0,%1,%2,%3}, [%4];" \
        : "=r"((r)[0]), "=r"((r)[1]), "=r"((r)[2]), "=r"((r)[3]) : "r"(addr))
#define MMA16816(d, a, b0, b1) \
    asm volatile("mma.sync.aligned.m16n8k16.row.col.f32.f16.f16.f32 " \
        "{%0,%1,%2,%3}, {%4,%5,%6,%7}, {%8,%9}, {%0,%1,%2,%3};" \
        : "+f"((d)[0]), "+f"((d)[1]), "+f"((d)[2]), "+f"((d)[3]) \
        : "r"((a)[0]), "r"((a)[1]), "r"((a)[2]), "r"((a)[3]), "r"(b0), "r"(b1))

// ---------------------------------------------------------------------------
// Kernel 0: convert QKV weights to fp16 (once per launch; 768 blocks, tiny)
// ---------------------------------------------------------------------------
__global__ void cvt_w(const float* __restrict__ We, const float* __restrict__ Wo)
{
    int i = blockIdx.x * 256 + threadIdx.x;
    if (i < 256 * 768) {
        g_Whe[i] = __float2half_rn(We[i]);
        g_Who[i] = __float2half_rn(Wo[i]);
    }
}

// ---------------------------------------------------------------------------
// Kernel 1: QKV projections, fp16 mma.sync m16n8k16 + ldmatrix.
// Grid: x = window (0..2303, ego then other), y = 128-col block (0..3).
// Block: 128 threads = 4 warps; warp tile 32 px x 64 cols; K-chunks of 32.
// A smem: [m=64][k=32] halves, row pitch 80B -> ldmatrix phases hit 8 distinct
//   bank groups ((5m+u) mod 8). B smem: [k=32][n=128] halves, 256B rows with
//   XOR swizzle u^= k&7 -> conflict-free STS.128 and ldmatrix.trans.
// ---------------------------------------------------------------------------
__global__ __launch_bounds__(128) void qkv_f16(
    const float* __restrict__ ego, const float* __restrict__ other)
{
    __shared__ __half As[64 * 40];    // pitch 40 halves = 80B
    __shared__ __half Bs[32 * 128];   // 256B rows, swizzled

    const int w = blockIdx.x;
    const int nb = blockIdx.y;
    const bool is_ego = (w < NWE);
    const float* src = is_ego ? ego + (size_t)w * (NC * NP)
                              : other + (size_t)(w - NWE) * (NC * NP);
    const __half* Wh = is_ego ? g_Whe : g_Who;
    // ego produced [q 0:256 | v 256:512] -> W cols {0:256, 512:768}; other: 256:768
    const int colbase = is_ego ? (nb < 2 ? nb * 128 : nb * 128 + 256) : (256 + nb * 128);

    const int t = threadIdx.x;
    const int warp = t >> 5, lane = t & 31;
    const int mbase = (warp >> 1) * 32;
    const int nbase = (warp & 1) * 64;
    const uint32_t as_b = smem_u32(As), bs_b = smem_u32(Bs);

    float acc[2][8][4];
    #pragma unroll
    for (int mt = 0; mt < 2; mt++)
        #pragma unroll
        for (int nt = 0; nt < 8; nt++)
            #pragma unroll
            for (int r = 0; r < 4; r++) acc[mt][nt][r] = 0.f;

    for (int c = 0; c < 8; c++) {
        __syncthreads();
        // stage A: 64 rows x 32 k; unit = 8 k-halves of one row (16B)
        #pragma unroll
        for (int ii = 0; ii < 2; ii++) {
            const int i = t + ii * 128;
            const int ku = i >> 6, m = i & 63;
            const int k0 = c * 32 + ku * 8;
            float v0 = src[(size_t)(k0 + 0) * NP + m];
            float v1 = src[(size_t)(k0 + 1) * NP + m];
            float v2 = src[(size_t)(k0 + 2) * NP + m];
            float v3 = src[(size_t)(k0 + 3) * NP + m];
            float v4 = src[(size_t)(k0 + 4) * NP + m];
            float v5 = src[(size_t)(k0 + 5) * NP + m];
            float v6 = src[(size_t)(k0 + 6) * NP + m];
            float v7 = src[(size_t)(k0 + 7) * NP + m];
            *(uint4*)&As[m * 40 + ku * 8] =
                make_uint4(pkh2(v0, v1), pkh2(v2, v3), pkh2(v4, v5), pkh2(v6, v7));
        }
        // stage B: 32 k x 128 n; unit = 8 n-halves (16B), swizzle u^=k&7
        #pragma unroll
        for (int ii = 0; ii < 4; ii++) {
            const int i = t + ii * 128;
            const int k = i >> 4, u = i & 15;
            uint4 v = *(const uint4*)&Wh[(size_t)(c * 32 + k) * 768 + colbase + u * 8];
            *(uint4*)&Bs[k * 128 + (u ^ (k & 7)) * 8] = v;
        }
        __syncthreads();

        #pragma unroll
        for (int ks = 0; ks < 2; ks++) {
            uint32_t a[2][4];
            #pragma unroll
            for (int mt = 0; mt < 2; mt++) {
                uint32_t ad = as_b + (mbase + mt * 16 + (lane & 15)) * 80
                            + (ks * 2 + (lane >> 4)) * 16;
                LDMX4(a[mt], ad);
            }
            uint32_t b[4][4];
            #pragma unroll
            for (int ng = 0; ng < 4; ng++) {
                const int kk = ks * 16 + (lane & 7) + ((lane >> 4) << 3);
                const int useg = ((nbase + ng * 16) >> 3) + ((lane >> 3) & 1);
                uint32_t bd = bs_b + kk * 256 + (useg ^ (kk & 7)) * 16;
                LDMX4T(b[ng], bd);
            }
            #pragma unroll
            for (int ng = 0; ng < 4; ng++)
                #pragma unroll
                for (int h2 = 0; h2 < 2; h2++) {
                    const int nt = ng * 2 + h2;
                    #pragma unroll
                    for (int mt = 0; mt < 2; mt++)
                        MMA16816(acc[mt][nt], a[mt], b[ng][h2], b[ng][2 + h2]);
                }
        }
    }

    // epilogue: scatter C frags (row = qid, cols 2*tid4 + {0,1}; +8 row pair)
    const int qid = lane >> 2, tid4 = lane & 3;
    int wo = w - NWE;
    int bo = wo >> 8, l = (wo >> 5) & 7, kk = wo & 31;
    const int bk = is_ego ? w : (bo * NK + kk);

    #pragma unroll
    for (int mt = 0; mt < 2; mt++) {
        int px = mbase + mt * 16 + qid;
        #pragma unroll
        for (int nt = 0; nt < 8; nt++) {
            int col = nb * 128 + nbase + nt * 8 + 2 * tid4;
            float2 v0 = make_float2(acc[mt][nt][0], acc[mt][nt][1]);
            float2 v1 = make_float2(acc[mt][nt][2], acc[mt][nt][3]);
            if (is_ego) {
                size_t i0 = ((size_t)bk * NP + px) * 512 + col;
                size_t i1 = ((size_t)bk * NP + px + 8) * 512 + col;
                *(float2*)&g_qv_e[i0] = v0;
                *(float2*)&g_qv_e[i1] = v1;
            } else {
                size_t i0 = (((size_t)bk * NP + px) * NL + l) * 512 + col;
                size_t i1 = (((size_t)bk * NP + px + 8) * NL + l) * 512 + col;
                *(float2*)&g_kv_o[i0] = v0;
                *(float2*)&g_kv_o[i1] = v1;
            }
        }
    }
}

// ---------------------------------------------------------------------------
// Kernel 2: attention. One block per pixel, 8 heads x 32 ch.
// q_o/k_e softmax over singleton ego axis == 1 -> only ego-query path needed.
// ---------------------------------------------------------------------------
__global__ __launch_bounds__(256) void attn_kernel()
{
    const int pix = blockIdx.x;
    const int t = threadIdx.x;

    const float q = g_qv_e[(size_t)pix * 512 + t];
    const size_t base = (size_t)pix * NL * 512;
    const float scale = 0.17677669529663687f;

    float scores[NL];
    #pragma unroll
    for (int l = 0; l < NL; l++) {
        float prod = q * g_kv_o[base + l * 512 + t];
        #pragma unroll
        for (int off = 16; off > 0; off >>= 1)
            prod += __shfl_xor_sync(0xffffffffu, prod, off);
        scores[l] = prod * scale;
    }
    float mx = scores[0];
    #pragma unroll
    for (int l = 1; l < NL; l++) mx = fmaxf(mx, scores[l]);
    float sum = 0.f;
    #pragma unroll
    for (int l = 0; l < NL; l++) { scores[l] = __expf(scores[l] - mx); sum += scores[l]; }
    const float inv = 1.f / sum;
    float o = 0.f;
    #pragma unroll
    for (int l = 0; l < NL; l++)
        o += scores[l] * inv * g_kv_o[base + l * 512 + 256 + t];
    g_o_e[(size_t)pix * NC + t] = o;
}

// ---------------------------------------------------------------------------
// Kernel 3: output projections + transposed store.
// mode 1 exploits softmax-over-singleton == identity: o_o == v_e, same for
// every l -> compute once, fan out 8 stores.
// ---------------------------------------------------------------------------
__global__ __launch_bounds__(256) void out_kernel(
    const float* __restrict__ Woe, const float* __restrict__ boe,
    const float* __restrict__ Woo, const float* __restrict__ boo,
    float* __restrict__ out)
{
    __shared__ float As2[32 * 68];
    __shared__ float Ws[32 * 64];

    const int x = blockIdx.x;
    const int bk = x >> 1;
    const int mode = x & 1;
    const float* Wm   = mode ? Woo : Woe;
    const float* bias = mode ? boo : boe;

    const int t = threadIdx.x;
    const int tj = t & 15;
    const int tp = t >> 4;

    for (int nc = 0; nc < 4; nc++) {
        float acc[4][4];
        #pragma unroll
        for (int i = 0; i < 4; i++)
            #pragma unroll
            for (int jx = 0; jx < 4; jx++) acc[i][jx] = 0.f;

        for (int c0 = 0; c0 < NC; c0 += 32) {
            __syncthreads();
            #pragma unroll
            for (int i = t; i < 2048; i += 256) {
                int jc = i & 31, p = i >> 5;
                float v = mode ? g_qv_e[((size_t)bk * NP + p) * 512 + 256 + c0 + jc]
                               : g_o_e [((size_t)bk * NP + p) * NC  +       c0 + jc];
                As2[jc * 68 + p] = v;
            }
            #pragma unroll
            for (int i = t; i < 512; i += 256) {
                int cc = i >> 4, j4 = (i & 15) * 4;
                *(float4*)&Ws[cc * 64 + j4] =
                    *(const float4*)&Wm[(size_t)(c0 + cc) * NC + nc * 64 + j4];
            }
            __syncthreads();
            #pragma unroll
            for (int cc = 0; cc < 32; cc++) {
                float4 a  = *(float4*)&As2[cc * 68 + tp * 4];
                float4 bb = *(float4*)&Ws[cc * 64 + tj * 4];
                acc[0][0] += a.x * bb.x; acc[0][1] += a.x * bb.y; acc[0][2] += a.x * bb.z; acc[0][3] += a.x * bb.w;
                acc[1][0] += a.y * bb.x; acc[1][1] += a.y * bb.y; acc[1][2] += a.y * bb.z; acc[1][3] += a.y * bb.w;
                acc[2][0] += a.z * bb.x; acc[2][1] += a.z * bb.y; acc[2][2] += a.z * bb.z; acc[2][3] += a.z * bb.w;
                acc[3][0] += a.w * bb.x; acc[3][1] += a.w * bb.y; acc[3][2] += a.w * bb.z; acc[3][3] += a.w * bb.w;
            }
        }
        #pragma unroll
        for (int jj = 0; jj < 4; jj++) {
            int cout = nc * 64 + tj * 4 + jj;
            float bv = bias[cout];
            float4 v = make_float4(acc[0][jj] + bv, acc[1][jj] + bv,
                                   acc[2][jj] + bv, acc[3][jj] + bv);
            if (mode == 0) {
                *(float4*)&out[((size_t)bk * NC + cout) * NP + tp * 4] = v;
            } else {
                int b = bk >> 5, k = bk & 31;
                #pragma unroll
                for (int l = 0; l < NL; l++) {
                    size_t idx = (size_t)EGO_OUT_SZ
                               + ((size_t)((b * NL + l) * NK + k) * NC + cout) * NP + tp * 4;
                    *(float4*)&out[idx] = v;
                }
            }
        }
    }
}

extern "C" void kernel_launch(void* const* d_in, const int* in_sizes, int n_in,
                              void* d_out, int out_size)
{
    const float* ego   = (const float*)d_in[0];
    const float* other = (const float*)d_in[1];
    const float* Wqe   = (const float*)d_in[2];
    const float* Wqo   = (const float*)d_in[3];
    const float* Woe   = (const float*)d_in[4];
    const float* boe   = (const float*)d_in[5];
    const float* Woo   = (const float*)d_in[6];
    const float* boo   = (const float*)d_in[7];
    float* out = (float*)d_out;

    cvt_w<<<768, 256>>>(Wqe, Wqo);
    dim3 qgrid(NWE + NWO, 4);
    qkv_f16<<<qgrid, 128>>>(ego, other);
    attn_kernel<<<NWE * NP, 256>>>();
    out_kernel<<<NWE * 2, 256>>>(Woe, boe, Woo, boo, out);
}

// round 11
// speedup vs baseline: 3.0463x; 1.1945x over previous
#include <cuda_runtime.h>
#include <cuda_fp16.h>
#include <cstdint>
#include <math.h>

// Problem constants
#define NB 8
#define NL 8
#define NK 32
#define NP 64
#define NC 256

#define NWE 256              // ego windows
#define NWO 2048             // other windows
#define EGO_OUT_SZ (NWE*NC*NP)

// Intermediates (static device memory; no allocation)
__device__ float g_qv_e[(size_t)NWE * NP * 512];
__device__ float g_kv_o[(size_t)NWE * NP * NL * 512];
__device__ float g_o_e [(size_t)NWE * NP * NC];
__device__ __half g_Whe[256 * 768];    // fp16 QKV weights
__device__ __half g_Who[256 * 768];
__device__ __half g_Whoe[256 * 256];   // fp16 out-proj weights
__device__ __half g_Whoo[256 * 256];

__device__ __forceinline__ uint32_t smem_u32(const void* p) {
    uint32_t a;
    asm("{ .reg .u64 t; cvta.to.shared.u64 t, %1; cvt.u32.u64 %0, t; }" : "=r"(a) : "l"(p));
    return a;
}
__device__ __forceinline__ uint32_t pkh2(float x, float y) {
    __half2 h = __floats2half2_rn(x, y);
    return *(uint32_t*)&h;
}

#define LDMX4(r, addr) \
    asm volatile("ldmatrix.sync.aligned.m8n8.x4.shared.b16 {%0,%1,%2,%3}, [%4];" \
        : "=r"((r)[0]), "=r"((r)[1]), "=r"((r)[2]), "=r"((r)[3]) : "r"(addr))
#define LDMX4T(r, addr) \
    asm volatile("ldmatrix.sync.aligned.m8n8.x4.trans.shared.b16 {%0,%1,%2,%3}, [%4];" \
        : "=r"((r)[0]), "=r"((r)[1]), "=r"((r)[2]), "=r"((r)[3]) : "r"(addr))
#define MMA16816(d, a, b0, b1) \
    asm volatile("mma.sync.aligned.m16n8k16.row.col.f32.f16.f16.f32 " \
        "{%0,%1,%2,%3}, {%4,%5,%6,%7}, {%8,%9}, {%0,%1,%2,%3};" \
        : "+f"((d)[0]), "+f"((d)[1]), "+f"((d)[2]), "+f"((d)[3]) \
        : "r"((a)[0]), "r"((a)[1]), "r"((a)[2]), "r"((a)[3]), "r"(b0), "r"(b1))

// ---------------------------------------------------------------------------
// Kernel 0: convert all weights to fp16 (once per launch, tiny)
// ---------------------------------------------------------------------------
__global__ void cvt_w(const float* __restrict__ We, const float* __restrict__ Wo,
                      const float* __restrict__ Woe, const float* __restrict__ Woo)
{
    int i = blockIdx.x * 256 + threadIdx.x;
    if (i < 256 * 768) {
        g_Whe[i] = __float2half_rn(We[i]);
        g_Who[i] = __float2half_rn(Wo[i]);
    }
    if (i < 256 * 256) {
        g_Whoe[i] = __float2half_rn(Woe[i]);
        g_Whoo[i] = __float2half_rn(Woo[i]);
    }
}

// ---------------------------------------------------------------------------
// Kernel 1: QKV projections, fp16 mma.sync m16n8k16 + ldmatrix (as round 9).
// ---------------------------------------------------------------------------
__global__ __launch_bounds__(128) void qkv_f16(
    const float* __restrict__ ego, const float* __restrict__ other)
{
    __shared__ __half As[64 * 40];    // pitch 40 halves = 80B
    __shared__ __half Bs[32 * 128];   // 256B rows, swizzled

    const int w = blockIdx.x;
    const int nb = blockIdx.y;
    const bool is_ego = (w < NWE);
    const float* src = is_ego ? ego + (size_t)w * (NC * NP)
                              : other + (size_t)(w - NWE) * (NC * NP);
    const __half* Wh = is_ego ? g_Whe : g_Who;
    const int colbase = is_ego ? (nb < 2 ? nb * 128 : nb * 128 + 256) : (256 + nb * 128);

    const int t = threadIdx.x;
    const int warp = t >> 5, lane = t & 31;
    const int mbase = (warp >> 1) * 32;
    const int nbase = (warp & 1) * 64;
    const uint32_t as_b = smem_u32(As), bs_b = smem_u32(Bs);

    float acc[2][8][4];
    #pragma unroll
    for (int mt = 0; mt < 2; mt++)
        #pragma unroll
        for (int nt = 0; nt < 8; nt++)
            #pragma unroll
            for (int r = 0; r < 4; r++) acc[mt][nt][r] = 0.f;

    for (int c = 0; c < 8; c++) {
        __syncthreads();
        #pragma unroll
        for (int ii = 0; ii < 2; ii++) {
            const int i = t + ii * 128;
            const int ku = i >> 6, m = i & 63;
            const int k0 = c * 32 + ku * 8;
            float v0 = src[(size_t)(k0 + 0) * NP + m];
            float v1 = src[(size_t)(k0 + 1) * NP + m];
            float v2 = src[(size_t)(k0 + 2) * NP + m];
            float v3 = src[(size_t)(k0 + 3) * NP + m];
            float v4 = src[(size_t)(k0 + 4) * NP + m];
            float v5 = src[(size_t)(k0 + 5) * NP + m];
            float v6 = src[(size_t)(k0 + 6) * NP + m];
            float v7 = src[(size_t)(k0 + 7) * NP + m];
            *(uint4*)&As[m * 40 + ku * 8] =
                make_uint4(pkh2(v0, v1), pkh2(v2, v3), pkh2(v4, v5), pkh2(v6, v7));
        }
        #pragma unroll
        for (int ii = 0; ii < 4; ii++) {
            const int i = t + ii * 128;
            const int k = i >> 4, u = i & 15;
            uint4 v = *(const uint4*)&Wh[(size_t)(c * 32 + k) * 768 + colbase + u * 8];
            *(uint4*)&Bs[k * 128 + (u ^ (k & 7)) * 8] = v;
        }
        __syncthreads();

        #pragma unroll
        for (int ks = 0; ks < 2; ks++) {
            uint32_t a[2][4];
            #pragma unroll
            for (int mt = 0; mt < 2; mt++) {
                uint32_t ad = as_b + (mbase + mt * 16 + (lane & 15)) * 80
                            + (ks * 2 + (lane >> 4)) * 16;
                LDMX4(a[mt], ad);
            }
            uint32_t b[4][4];
            #pragma unroll
            for (int ng = 0; ng < 4; ng++) {
                const int kk = ks * 16 + (lane & 7) + ((lane >> 4) << 3);
                const int useg = ((nbase + ng * 16) >> 3) + ((lane >> 3) & 1);
                uint32_t bd = bs_b + kk * 256 + (useg ^ (kk & 7)) * 16;
                LDMX4T(b[ng], bd);
            }
            #pragma unroll
            for (int ng = 0; ng < 4; ng++)
                #pragma unroll
                for (int h2 = 0; h2 < 2; h2++) {
                    const int nt = ng * 2 + h2;
                    #pragma unroll
                    for (int mt = 0; mt < 2; mt++)
                        MMA16816(acc[mt][nt], a[mt], b[ng][h2], b[ng][2 + h2]);
                }
        }
    }

    const int qid = lane >> 2, tid4 = lane & 3;
    int wo = w - NWE;
    int bo = wo >> 8, l = (wo >> 5) & 7, kk2 = wo & 31;
    const int bk = is_ego ? w : (bo * NK + kk2);

    #pragma unroll
    for (int mt = 0; mt < 2; mt++) {
        int px = mbase + mt * 16 + qid;
        #pragma unroll
        for (int nt = 0; nt < 8; nt++) {
            int col = nb * 128 + nbase + nt * 8 + 2 * tid4;
            float2 v0 = make_float2(acc[mt][nt][0], acc[mt][nt][1]);
            float2 v1 = make_float2(acc[mt][nt][2], acc[mt][nt][3]);
            if (is_ego) {
                size_t i0 = ((size_t)bk * NP + px) * 512 + col;
                size_t i1 = ((size_t)bk * NP + px + 8) * 512 + col;
                *(float2*)&g_qv_e[i0] = v0;
                *(float2*)&g_qv_e[i1] = v1;
            } else {
                size_t i0 = (((size_t)bk * NP + px) * NL + l) * 512 + col;
                size_t i1 = (((size_t)bk * NP + px + 8) * NL + l) * 512 + col;
                *(float2*)&g_kv_o[i0] = v0;
                *(float2*)&g_kv_o[i1] = v1;
            }
        }
    }
}

// ---------------------------------------------------------------------------
// Kernel 2: attention (unchanged). q_o/k_e path is the identity (softmax over
// singleton ego axis == 1), so only the ego-query path is computed.
// ---------------------------------------------------------------------------
__global__ __launch_bounds__(256) void attn_kernel()
{
    const int pix = blockIdx.x;
    const int t = threadIdx.x;

    const float q = g_qv_e[(size_t)pix * 512 + t];
    const size_t base = (size_t)pix * NL * 512;
    const float scale = 0.17677669529663687f;

    float scores[NL];
    #pragma unroll
    for (int l = 0; l < NL; l++) {
        float prod = q * g_kv_o[base + l * 512 + t];
        #pragma unroll
        for (int off = 16; off > 0; off >>= 1)
            prod += __shfl_xor_sync(0xffffffffu, prod, off);
        scores[l] = prod * scale;
    }
    float mx = scores[0];
    #pragma unroll
    for (int l = 1; l < NL; l++) mx = fmaxf(mx, scores[l]);
    float sum = 0.f;
    #pragma unroll
    for (int l = 0; l < NL; l++) { scores[l] = __expf(scores[l] - mx); sum += scores[l]; }
    const float inv = 1.f / sum;
    float o = 0.f;
    #pragma unroll
    for (int l = 0; l < NL; l++)
        o += scores[l] * inv * g_kv_o[base + l * 512 + 256 + t];
    g_o_e[(size_t)pix * NC + t] = o;
}

// ---------------------------------------------------------------------------
// Kernel 3: output projections on fp16 mma.sync, smem-transposed epilogue.
// Grid: x = bk*2+mode (512), y = n-half (0..1). Block 128 thr / 4 warps.
// M=64 px, N=128 cout, K=256. mode 1: o_o == v_e (softmax over singleton
// axis == identity), identical for all l -> compute once, fan out 8 stores.
// ---------------------------------------------------------------------------
__global__ __launch_bounds__(128) void out_f16(
    const float* __restrict__ boe, const float* __restrict__ boo,
    float* __restrict__ out)
{
    __shared__ __half As[64 * 40];
    __shared__ __half Bs[32 * 128];
    __shared__ float  Cs[128 * 68];   // [n][p], pad 68: conflict-free + aligned

    const int x = blockIdx.x;
    const int nb = blockIdx.y;
    const int bk = x >> 1;
    const int mode = x & 1;
    const __half* Wh  = mode ? g_Whoo : g_Whoe;
    const float* bias = mode ? boo : boe;
    // A source: mode0 = g_o_e[bk][p][c]; mode1 = v_e slice of g_qv_e
    const float* asrc = mode ? (g_qv_e + (size_t)bk * NP * 512 + 256)
                             : (g_o_e  + (size_t)bk * NP * NC);
    const size_t astride = mode ? 512 : 256;
    const int colbase = nb * 128;

    const int t = threadIdx.x;
    const int warp = t >> 5, lane = t & 31;
    const int mbase = (warp >> 1) * 32;
    const int nbase = (warp & 1) * 64;
    const uint32_t as_b = smem_u32(As), bs_b = smem_u32(Bs);

    float acc[2][8][4];
    #pragma unroll
    for (int mt = 0; mt < 2; mt++)
        #pragma unroll
        for (int nt = 0; nt < 8; nt++)
            #pragma unroll
            for (int r = 0; r < 4; r++) acc[mt][nt][r] = 0.f;

    for (int c = 0; c < 8; c++) {
        __syncthreads();
        // stage A: 64 p-rows x 32 k (k contiguous in source -> (m,ku) map coalesced)
        #pragma unroll
        for (int ii = 0; ii < 2; ii++) {
            const int i = t + ii * 128;
            const int m = i >> 2, ku = i & 3;
            const float* r = asrc + (size_t)m * astride + c * 32 + ku * 8;
            float4 u0 = *(const float4*)r;
            float4 u1 = *(const float4*)(r + 4);
            *(uint4*)&As[m * 40 + ku * 8] =
                make_uint4(pkh2(u0.x, u0.y), pkh2(u0.z, u0.w),
                           pkh2(u1.x, u1.y), pkh2(u1.z, u1.w));
        }
        // stage B: 32 k x 128 n, swizzled (fp16 weights, row stride 256)
        #pragma unroll
        for (int ii = 0; ii < 4; ii++) {
            const int i = t + ii * 128;
            const int k = i >> 4, u = i & 15;
            uint4 v = *(const uint4*)&Wh[(size_t)(c * 32 + k) * 256 + colbase + u * 8];
            *(uint4*)&Bs[k * 128 + (u ^ (k & 7)) * 8] = v;
        }
        __syncthreads();

        #pragma unroll
        for (int ks = 0; ks < 2; ks++) {
            uint32_t a[2][4];
            #pragma unroll
            for (int mt = 0; mt < 2; mt++) {
                uint32_t ad = as_b + (mbase + mt * 16 + (lane & 15)) * 80
                            + (ks * 2 + (lane >> 4)) * 16;
                LDMX4(a[mt], ad);
            }
            uint32_t b[4][4];
            #pragma unroll
            for (int ng = 0; ng < 4; ng++) {
                const int kk = ks * 16 + (lane & 7) + ((lane >> 4) << 3);
                const int useg = ((nbase + ng * 16) >> 3) + ((lane >> 3) & 1);
                uint32_t bd = bs_b + kk * 256 + (useg ^ (kk & 7)) * 16;
                LDMX4T(b[ng], bd);
            }
            #pragma unroll
            for (int ng = 0; ng < 4; ng++)
                #pragma unroll
                for (int h2 = 0; h2 < 2; h2++) {
                    const int nt = ng * 2 + h2;
                    #pragma unroll
                    for (int mt = 0; mt < 2; mt++)
                        MMA16816(acc[mt][nt], a[mt], b[ng][h2], b[ng][2 + h2]);
                }
        }
    }

    // transpose through smem: Cs[n][p]
    const int qid = lane >> 2, tid4 = lane & 3;
    __syncthreads();
    #pragma unroll
    for (int mt = 0; mt < 2; mt++) {
        const int p = mbase + mt * 16 + qid;
        #pragma unroll
        for (int nt = 0; nt < 8; nt++) {
            const int n = nbase + nt * 8 + 2 * tid4;
            Cs[(n    ) * 68 + p    ] = acc[mt][nt][0];
            Cs[(n + 1) * 68 + p    ] = acc[mt][nt][1];
            Cs[(n    ) * 68 + p + 8] = acc[mt][nt][2];
            Cs[(n + 1) * 68 + p + 8] = acc[mt][nt][3];
        }
    }
    __syncthreads();

    // coalesced write: thread t owns cout = colbase + t, 64 p-floats (+bias)
    {
        const int cout = colbase + t;
        const float bv = bias[cout];
        if (mode == 0) {
            float* dst = out + ((size_t)bk * NC + cout) * NP;
            #pragma unroll
            for (int i = 0; i < 16; i++) {
                float4 v = *(float4*)&Cs[t * 68 + 4 * i];
                *(float4*)&dst[4 * i] =
                    make_float4(v.x + bv, v.y + bv, v.z + bv, v.w + bv);
            }
        } else {
            const int b = bk >> 5, k = bk & 31;
            #pragma unroll
            for (int i = 0; i < 16; i++) {
                float4 v = *(float4*)&Cs[t * 68 + 4 * i];
                float4 vb = make_float4(v.x + bv, v.y + bv, v.z + bv, v.w + bv);
                #pragma unroll
                for (int l = 0; l < NL; l++) {
                    size_t idx = (size_t)EGO_OUT_SZ
                               + ((size_t)((b * NL + l) * NK + k) * NC + cout) * NP + 4 * i;
                    *(float4*)&out[idx] = vb;
                }
            }
        }
    }
}

extern "C" void kernel_launch(void* const* d_in, const int* in_sizes, int n_in,
                              void* d_out, int out_size)
{
    const float* ego   = (const float*)d_in[0];
    const float* other = (const float*)d_in[1];
    const float* Wqe   = (const float*)d_in[2];
    const float* Wqo   = (const float*)d_in[3];
    const float* Woe   = (const float*)d_in[4];
    const float* boe   = (const float*)d_in[5];
    const float* Woo   = (const float*)d_in[6];
    const float* boo   = (const float*)d_in[7];
    float* out = (float*)d_out;

    cvt_w<<<768, 256>>>(Wqe, Wqo, Woe, Woo);
    dim3 qgrid(NWE + NWO, 4);
    qkv_f16<<<qgrid, 128>>>(ego, other);
    attn_kernel<<<NWE * NP, 256>>>();
    dim3 ogrid(NWE * 2, 2);
    out_f16<<<ogrid, 128>>>(boe, boo, out);
}